// round 9
// baseline (speedup 1.0000x reference)
#include <cuda_runtime.h>
#include <cuda_fp16.h>
#include <math.h>
#include <cstdint>

// ---------------- problem constants ----------------------------------------
#define NB    8
#define Cc    256
#define HW    961
#define Mrows 7688
#define MP    7808          // padded M = 61*128
#define HID   512
#define OUTF  256

// ---------------- scratch (device globals; zero-initialized) ----------------
__device__ float    g_S0  [NB * Cc];
__device__ uint32_t g_YP  [(Cc / 2) * MP];     // packed fp16x2 (k even|odd)
__device__ uint32_t g_W1hP[(Cc / 2) * HID];    // weights fp16x2 packed [k/2][n]
__device__ uint32_t g_W2hP[(HID / 2) * OUTF];
__device__ float    g_H1T [HID * MP];
__device__ float    g_S1T [HID * 16];
__device__ float    g_H2T [OUTF * MP];

// ---------------- helpers ----------------------------------------------------
__device__ __forceinline__ uint32_t smem_u32(const void* p) {
    uint32_t a;
    asm("{ .reg .u64 t; cvta.to.shared.u64 t, %1; cvt.u32.u64 %0, t; }"
        : "=r"(a) : "l"(p));
    return a;
}

__device__ __forceinline__ float dinv_of(int b) {
    int deg = (b == 0 || b == NB - 1) ? 963 : 964;
    return 1.0f / sqrtf((float)deg);
}

__device__ __forceinline__ uint32_t f16x2_pack(float v0, float v1) {
    __half2 h = __floats2half2_rn(v0, v1);
    return *(uint32_t*)&h;
}

#define MMA_F16(d, a, b) \
    asm volatile("mma.sync.aligned.m16n8k16.row.col.f32.f16.f16.f32 " \
                 "{%0,%1,%2,%3},{%4,%5,%6,%7},{%8,%9},{%0,%1,%2,%3};" \
                 : "+f"((d)[0]), "+f"((d)[1]), "+f"((d)[2]), "+f"((d)[3]) \
                 : "r"((a)[0]), "r"((a)[1]), "r"((a)[2]), "r"((a)[3]), \
                   "r"((b)[0]), "r"((b)[1]))

#define CP_ASYNC16(dst32, src) \
    asm volatile("cp.async.cg.shared.global [%0], [%1], 16;" :: "r"(dst32), "l"(src))
#define CP_COMMIT()  asm volatile("cp.async.commit_group;" ::: "memory")
#define CP_WAIT1()   asm volatile("cp.async.wait_group 1;" ::: "memory")

// ---------------- small kernels ----------------------------------------------
__global__ void sum_x_kernel(const float* __restrict__ x, float* __restrict__ S0) {
    int bc = blockIdx.x;
    const float* src = x + (size_t)bc * HW;
    float s = 0.f;
    for (int p = threadIdx.x; p < HW; p += 256) s += src[p];
    __shared__ float red[8];
    #pragma unroll
    for (int off = 16; off; off >>= 1) s += __shfl_down_sync(0xffffffffu, s, off);
    if ((threadIdx.x & 31) == 0) red[threadIdx.x >> 5] = s;
    __syncthreads();
    if (threadIdx.x < 8) {
        s = red[threadIdx.x];
        #pragma unroll
        for (int off = 4; off; off >>= 1) s += __shfl_down_sync(0xffu, s, off);
        if (threadIdx.x == 0) S0[bc] = s;
    }
}

// W[Nr][Kc] row-major -> packed fp16x2 [Kc/2][Nr]
__global__ void wsplit_p(const float* __restrict__ W,
                         uint32_t* __restrict__ WhP, int Nr, int Kc) {
    __shared__ float t[32][33];
    int n0 = blockIdx.x * 32, k0 = blockIdx.y * 32;
    int tx = threadIdx.x, ty = threadIdx.y;
    #pragma unroll
    for (int r = 0; r < 4; r++)
        t[ty + 8 * r][tx] = W[(size_t)(n0 + ty + 8 * r) * Kc + k0 + tx];
    __syncthreads();
    #pragma unroll
    for (int r = 0; r < 2; r++) {
        int k2l = ty + 8 * r;                 // 0..15
        size_t o = (size_t)(k0 / 2 + k2l) * Nr + n0 + tx;
        WhP[o] = f16x2_pack(t[tx][2 * k2l], t[tx][2 * k2l + 1]);
    }
}

// aggregation on x -> packed fp16x2 [Cc/2][MP], 4 m per thread
__global__ void agg_x_f16(const float* __restrict__ x, const float* __restrict__ S0,
                          uint32_t* __restrict__ YP) {
    int c2 = blockIdx.y;                      // 0..127
    int m0 = (blockIdx.x * 256 + threadIdx.x) * 4;
    if (m0 >= Mrows) return;
    const int c = 2 * c2;
    uint32_t w[4];
    int b0 = m0 / HW;
    int b3 = (m0 + 3 < Mrows ? (m0 + 3) : (Mrows - 1)) / HW;
    if (b0 == b3 && m0 + 3 < Mrows) {
        // fast path: all 4 nodes in same sample
        int b = b0, p = m0 - b * HW;
        float db = dinv_of(b);
        float k0 = db * db;
        float cm = (b > 0)      ? db * dinv_of(b - 1) : 0.f;
        float cp = (b < NB - 1) ? db * dinv_of(b + 1) : 0.f;
        #pragma unroll
        for (int e = 0; e < 2; e++) {
            const float* xr = x + (size_t)(b * Cc + c + e) * HW + p;
            float s0 = S0[b * Cc + c + e];
            #pragma unroll
            for (int j = 0; j < 4; j++) {
                float vv = k0 * (s0 + __ldg(xr + j));
                if (b > 0)      vv += cm * __ldg(xr + j - Cc * HW);
                if (b < NB - 1) vv += cp * __ldg(xr + j + Cc * HW);
                if (e == 0) w[j] = (uint32_t)__half_as_ushort(__float2half_rn(vv));
                else        w[j] |= ((uint32_t)__half_as_ushort(__float2half_rn(vv))) << 16;
            }
        }
    } else {
        #pragma unroll
        for (int j = 0; j < 4; j++) {
            int m = m0 + j;
            if (m >= Mrows) { w[j] = 0; continue; }
            int b = m / HW, p = m - b * HW;
            float db = dinv_of(b);
            float k0 = db * db;
            float v2[2];
            #pragma unroll
            for (int e = 0; e < 2; e++) {
                size_t xi = (size_t)(b * Cc + c + e) * HW + p;
                float vv = k0 * (S0[b * Cc + c + e] + __ldg(&x[xi]));
                if (b > 0)      vv += db * dinv_of(b - 1) * __ldg(&x[xi - (size_t)Cc * HW]);
                if (b < NB - 1) vv += db * dinv_of(b + 1) * __ldg(&x[xi + (size_t)Cc * HW]);
                v2[e] = vv;
            }
            w[j] = f16x2_pack(v2[0], v2[1]);
        }
    }
    *(uint4*)(YP + (size_t)c2 * MP + m0) = make_uint4(w[0], w[1], w[2], w[3]);
}

// per-(feature, sample) sums of H1T rows -> S1T[k][16]
__global__ void sum_h(const float* __restrict__ H1T, float* __restrict__ S1T) {
    int k = blockIdx.x;
    int w = threadIdx.x >> 5, lane = threadIdx.x & 31;
    const float* src = H1T + (size_t)k * MP + w * HW;
    float s = 0.f;
    #pragma unroll 8
    for (int p = lane; p < HW; p += 32) s += src[p];
    #pragma unroll
    for (int off = 16; off; off >>= 1) s += __shfl_down_sync(0xffffffffu, s, off);
    if (lane == 0) S1T[k * 16 + w] = s;
}

// max over samples
__global__ void max_k(const float* __restrict__ H2T, float* __restrict__ out) {
    int idx = blockIdx.x * 256 + threadIdx.x;
    if (idx >= OUTF * HW) return;
    int o = idx / HW, p = idx - o * HW;
    const float* src = H2T + (size_t)o * MP + p;
    float m = -INFINITY;
    #pragma unroll
    for (int b = 0; b < NB; b++) m = fmaxf(m, src[b * HW]);
    out[idx] = m;
}

// ---------------- fp16 mma.sync GEMM, 128x128 CTA tile, 64x32 warp tile ------
// C^T[n][m] = lrelu( sum_k A[m][k]*W[n][k] + bias[n] )
// A fp16x2 packed [k/2][m]; W fp16x2 packed [k/2][n].
// AGG: A built on the fly from H1T (fp32 k-major) + S1T per-sample sums.
template<int KTOT, int NTOT, bool AGG>
__global__ __launch_bounds__(256)
void gemm_mma(const uint32_t* __restrict__ AP,
              const float* __restrict__ H1T, const float* __restrict__ S1T,
              const uint32_t* __restrict__ BhP,
              const float* __restrict__ bias, float* __restrict__ CT) {
    extern __shared__ uint32_t smu[];
    constexpr int ROWW  = 136;             // words per k2-row (128 + 8 pad)
    constexpr int ATILE = 16 * ROWW;       // 2176
    constexpr int BTILE = 16 * ROWW;       // 2176
    constexpr int BUFW  = ATILE + BTILE;   // 4352 words
    constexpr int NC    = KTOT / 32;

    const int tid  = threadIdx.x;
    const int lane = tid & 31;
    const int wid  = tid >> 5;
    const int bm   = blockIdx.y * 128;
    const int bn   = blockIdx.x * 128;
    const int wm   = (wid & 1) * 64;
    const int wn   = (wid >> 1) * 32;
    const int g    = lane >> 2, tg = lane & 3;
    const uint32_t sb = smem_u32(smu);

    float acc[4][4][4];
    #pragma unroll
    for (int i = 0; i < 4; i++)
        #pragma unroll
        for (int j = 0; j < 4; j++)
            #pragma unroll
            for (int e = 0; e < 4; e++) acc[i][j][e] = 0.f;

    auto load_chunk = [&](int ch) {
        const int st   = ch & 1;
        const int k2_0 = ch * 16;
        const uint32_t bufb = sb + (uint32_t)(st * BUFW) * 4;
        // B tile via cp.async: 16 k2-rows x 128 words, 2 ops/thread
        #pragma unroll
        for (int i = 0; i < 2; i++) {
            int q   = tid + i * 256;       // 0..511
            int row = q >> 5, c = q & 31;
            const uint32_t* src = BhP + (size_t)(k2_0 + row) * NTOT + bn + c * 4;
            uint32_t dst = bufb + (uint32_t)(ATILE + row * ROWW + c * 4) * 4;
            CP_ASYNC16(dst, src);
        }
        if (!AGG) {
            // A tile via cp.async: 16 k2-rows x 128 words, 2 ops/thread
            #pragma unroll
            for (int i = 0; i < 2; i++) {
                int q   = tid + i * 256;
                int row = q >> 5, c = q & 31;
                const uint32_t* src = AP + (size_t)(k2_0 + row) * MP + bm + c * 4;
                uint32_t dst = bufb + (uint32_t)(row * ROWW + c * 4) * 4;
                CP_ASYNC16(dst, src);
            }
        } else {
            // A computed: agg(H1) -> fp16x2, 16 k2-rows x 128 m
            uint32_t* bA = smu + st * BUFW;
            const int k0 = ch * 32;
            #pragma unroll
            for (int i = 0; i < 8; i++) {
                int q   = tid + i * 256;   // 0..2047
                int k2l = q >> 7;          // 0..15
                int mi  = q & 127;
                int k   = k0 + 2 * k2l;
                int m   = bm + mi;
                int b = m / HW; if (b > NB - 1) b = NB - 1;
                float db = dinv_of(b);
                float c0 = db * db;
                float cm = (b > 0)      ? db * dinv_of(b - 1) : 0.f;
                float cp = (b < NB - 1) ? db * dinv_of(b + 1) : 0.f;
                const float* h0 = H1T + (size_t)k * MP + m;
                const float* h1 = h0 + MP;
                float v0 = c0 * (__ldg(&S1T[k * 16 + b]) + __ldg(h0));
                float v1 = c0 * (__ldg(&S1T[(k + 1) * 16 + b]) + __ldg(h1));
                if (b > 0) {
                    v0 += cm * __ldg(h0 - HW);
                    v1 += cm * __ldg(h1 - HW);
                }
                if (b < NB - 1) {
                    v0 += cp * __ldg(h0 + HW);
                    v1 += cp * __ldg(h1 + HW);
                }
                bA[k2l * ROWW + mi] = f16x2_pack(v0, v1);
            }
        }
    };

    // prologue
    load_chunk(0);
    CP_COMMIT();

    for (int ch = 0; ch < NC; ch++) {
        if (ch + 1 < NC) load_chunk(ch + 1);
        CP_COMMIT();
        CP_WAIT1();
        __syncthreads();

        const uint32_t* Ab = smu + (ch & 1) * BUFW;
        const uint32_t* Bh = Ab + ATILE;

        #pragma unroll
        for (int kk = 0; kk < 2; kk++) {
            const int kb = kk * 8;
            uint32_t a[4][4], bh[4][2];
            #pragma unroll
            for (int mt = 0; mt < 4; mt++) {
                int mb = wm + mt * 16 + g;
                a[mt][0] = Ab[(kb + tg) * ROWW + mb];
                a[mt][1] = Ab[(kb + tg) * ROWW + mb + 8];
                a[mt][2] = Ab[(kb + tg + 4) * ROWW + mb];
                a[mt][3] = Ab[(kb + tg + 4) * ROWW + mb + 8];
            }
            #pragma unroll
            for (int nt = 0; nt < 4; nt++) {
                int nb = wn + nt * 8 + g;
                bh[nt][0] = Bh[(kb + tg) * ROWW + nb];
                bh[nt][1] = Bh[(kb + tg + 4) * ROWW + nb];
            }
            #pragma unroll
            for (int mt = 0; mt < 4; mt++)
                #pragma unroll
                for (int nt = 0; nt < 4; nt++)
                    MMA_F16(acc[mt][nt], a[mt], bh[nt]);
        }
        __syncthreads();
    }

    // epilogue: bias + leaky relu, store transposed CT[n][m]
    #pragma unroll
    for (int mt = 0; mt < 4; mt++) {
        int m0 = bm + wm + mt * 16 + g;
        bool v0 = m0 < Mrows, v8 = (m0 + 8) < Mrows;
        #pragma unroll
        for (int nt = 0; nt < 4; nt++) {
            int n = bn + wn + nt * 8 + 2 * tg;
            float bb0 = __ldg(&bias[n]), bb1 = __ldg(&bias[n + 1]);
            float c0 = acc[mt][nt][0] + bb0;
            float c1 = acc[mt][nt][1] + bb1;
            float c2 = acc[mt][nt][2] + bb0;
            float c3 = acc[mt][nt][3] + bb1;
            c0 = c0 > 0.f ? c0 : 0.01f * c0;
            c1 = c1 > 0.f ? c1 : 0.01f * c1;
            c2 = c2 > 0.f ? c2 : 0.01f * c2;
            c3 = c3 > 0.f ? c3 : 0.01f * c3;
            if (v0) {
                CT[(size_t)n * MP + m0]       = c0;
                CT[(size_t)(n + 1) * MP + m0] = c1;
            }
            if (v8) {
                CT[(size_t)n * MP + m0 + 8]       = c2;
                CT[(size_t)(n + 1) * MP + m0 + 8] = c3;
            }
        }
    }
}

// ---------------- launcher ----------------------------------------------------
extern "C" void kernel_launch(void* const* d_in, const int* in_sizes, int n_in,
                              void* d_out, int out_size) {
    const float* x  = (const float*)d_in[0];
    const float* W1 = (const float*)d_in[1];
    const float* b1 = (const float*)d_in[2];
    const float* W2 = (const float*)d_in[3];
    const float* b2 = (const float*)d_in[4];
    float* out = (float*)d_out;

    float *S0, *H1T, *S1T, *H2T;
    uint32_t *YP, *W1h, *W2h;
    cudaGetSymbolAddress((void**)&S0,  g_S0);
    cudaGetSymbolAddress((void**)&YP,  g_YP);
    cudaGetSymbolAddress((void**)&W1h, g_W1hP);
    cudaGetSymbolAddress((void**)&W2h, g_W2hP);
    cudaGetSymbolAddress((void**)&H1T, g_H1T);
    cudaGetSymbolAddress((void**)&S1T, g_S1T);
    cudaGetSymbolAddress((void**)&H2T, g_H2T);

    constexpr int SMEM = 2 * 4352 * 4;   // 34816 B
    cudaFuncSetAttribute(gemm_mma<Cc,  HID,  false>,
                         cudaFuncAttributeMaxDynamicSharedMemorySize, SMEM);
    cudaFuncSetAttribute(gemm_mma<HID, OUTF, true>,
                         cudaFuncAttributeMaxDynamicSharedMemorySize, SMEM);

    // 1) per-sample channel sums of x; weight transpose to packed fp16x2
    sum_x_kernel<<<NB * Cc, 256>>>(x, S0);
    wsplit_p<<<dim3(HID / 32, Cc / 32), dim3(32, 8)>>>(W1, W1h, HID, Cc);
    wsplit_p<<<dim3(OUTF / 32, HID / 32), dim3(32, 8)>>>(W2, W2h, OUTF, HID);

    // 2) aggregation on x -> packed fp16 Y (4 m per thread)
    agg_x_f16<<<dim3((Mrows + 1023) / 1024, Cc / 2), 256>>>(x, S0, YP);

    // 3) GEMM1: H1T = lrelu(Y @ W1^T + b1)^T
    gemm_mma<Cc, HID, false><<<dim3(HID / 128, MP / 128), 256, SMEM>>>(
        YP, nullptr, nullptr, W1h, b1, H1T);

    // 4) per-sample sums of H1
    sum_h<<<HID, 256>>>(H1T, S1T);

    // 5) GEMM2 (fused aggregation): H2T = lrelu(agg(H1) @ W2^T + b2)^T
    gemm_mma<HID, OUTF, true><<<dim3(OUTF / 128, MP / 128), 256, SMEM>>>(
        nullptr, H1T, S1T, W2h, b2, H2T);

    // 6) max over samples
    max_k<<<(OUTF * HW + 255) / 256, 256>>>(H2T, out);
}

// round 11
// speedup vs baseline: 1.2909x; 1.2909x over previous
#include <cuda_runtime.h>
#include <cuda_fp16.h>
#include <math.h>
#include <cstdint>

// ---------------- problem constants ----------------------------------------
#define NB    8
#define Cc    256
#define HW    961
#define Mrows 7688
#define MP    7808          // padded M = 61*128
#define HID   512
#define OUTF  256

// ---------------- scratch (device globals; zero-initialized) ----------------
__device__ float    g_S0  [NB * Cc];
__device__ uint32_t g_YP  [MP * (Cc / 2)];     // m-major packed fp16x2 [m][k2]
__device__ uint32_t g_W1hP[HID * (Cc / 2)];    // n-major packed [n][k2]
__device__ uint32_t g_W2hP[OUTF * (HID / 2)];
__device__ float    g_H1T [HID * MP];
__device__ float    g_S1T [HID * 16];
__device__ float    g_H2T [OUTF * MP];

// ---------------- helpers ----------------------------------------------------
__device__ __forceinline__ uint32_t smem_u32(const void* p) {
    uint32_t a;
    asm("{ .reg .u64 t; cvta.to.shared.u64 t, %1; cvt.u32.u64 %0, t; }"
        : "=r"(a) : "l"(p));
    return a;
}

__device__ __forceinline__ float dinv_of(int b) {
    int deg = (b == 0 || b == NB - 1) ? 963 : 964;
    return 1.0f / sqrtf((float)deg);
}

__device__ __forceinline__ uint32_t f16x2_pack(float v0, float v1) {
    __half2 h = __floats2half2_rn(v0, v1);
    return *(uint32_t*)&h;
}

#define MMA_F16(d, a0, a1, a2, a3, b0, b1) \
    asm volatile("mma.sync.aligned.m16n8k16.row.col.f32.f16.f16.f32 " \
                 "{%0,%1,%2,%3},{%4,%5,%6,%7},{%8,%9},{%0,%1,%2,%3};" \
                 : "+f"((d)[0]), "+f"((d)[1]), "+f"((d)[2]), "+f"((d)[3]) \
                 : "r"(a0), "r"(a1), "r"(a2), "r"(a3), "r"(b0), "r"(b1))

#define LDSM_X4(r0, r1, r2, r3, addr) \
    asm volatile("ldmatrix.sync.aligned.m8n8.x4.shared.b16 {%0,%1,%2,%3}, [%4];" \
                 : "=r"(r0), "=r"(r1), "=r"(r2), "=r"(r3) : "r"(addr))

#define CP_ASYNC16(dst32, src) \
    asm volatile("cp.async.cg.shared.global [%0], [%1], 16;" :: "r"(dst32), "l"(src))
#define CP_COMMIT()  asm volatile("cp.async.commit_group;" ::: "memory")
#define CP_WAIT1()   asm volatile("cp.async.wait_group 1;" ::: "memory")

// ---------------- small kernels ----------------------------------------------
__global__ void sum_x_kernel(const float* __restrict__ x, float* __restrict__ S0) {
    int bc = blockIdx.x;
    const float* src = x + (size_t)bc * HW;
    float s = 0.f;
    for (int p = threadIdx.x; p < HW; p += 256) s += src[p];
    __shared__ float red[8];
    #pragma unroll
    for (int off = 16; off; off >>= 1) s += __shfl_down_sync(0xffffffffu, s, off);
    if ((threadIdx.x & 31) == 0) red[threadIdx.x >> 5] = s;
    __syncthreads();
    if (threadIdx.x < 8) {
        s = red[threadIdx.x];
        #pragma unroll
        for (int off = 4; off; off >>= 1) s += __shfl_down_sync(0xffu, s, off);
        if (threadIdx.x == 0) S0[bc] = s;
    }
}

// W[Nr][Kc] row-major fp32 -> packed fp16x2 [n][k2] (pure linear pack)
__global__ void wsplit_lin(const float* __restrict__ W, uint32_t* __restrict__ WhP,
                           int total2) {
    int i = blockIdx.x * 256 + threadIdx.x;
    if (i < total2) {
        float2 v = ((const float2*)W)[i];
        WhP[i] = f16x2_pack(v.x, v.y);
    }
}

// aggregation on x -> m-major packed fp16x2 [m][Cc/2]; 8 channels per thread
__global__ void agg_x_f16(const float* __restrict__ x, const float* __restrict__ S0,
                          uint32_t* __restrict__ YP) {
    int m  = blockIdx.x * 256 + threadIdx.x;
    if (m >= Mrows) return;
    int cq = blockIdx.y;                      // 0..31: channels 8*cq .. 8*cq+7
    int b = m / HW, p = m - b * HW;
    float db = dinv_of(b);
    float c0 = db * db;
    float cm = (b > 0)      ? db * dinv_of(b - 1) : 0.f;
    float cp = (b < NB - 1) ? db * dinv_of(b + 1) : 0.f;
    uint32_t w[4];
    #pragma unroll
    for (int j = 0; j < 4; j++) {
        float v2[2];
        #pragma unroll
        for (int e = 0; e < 2; e++) {
            int c = cq * 8 + j * 2 + e;
            size_t xi = (size_t)(b * Cc + c) * HW + p;
            float vv = c0 * (__ldg(&S0[b * Cc + c]) + __ldg(&x[xi]));
            if (b > 0)      vv += cm * __ldg(&x[xi - (size_t)Cc * HW]);
            if (b < NB - 1) vv += cp * __ldg(&x[xi + (size_t)Cc * HW]);
            v2[e] = vv;
        }
        w[j] = f16x2_pack(v2[0], v2[1]);
    }
    *(uint4*)(YP + (size_t)m * (Cc / 2) + cq * 4) = make_uint4(w[0], w[1], w[2], w[3]);
}

// per-(feature, sample) sums of H1T rows -> S1T[k][16]
__global__ void sum_h(const float* __restrict__ H1T, float* __restrict__ S1T) {
    int k = blockIdx.x;
    int w = threadIdx.x >> 5, lane = threadIdx.x & 31;
    const float* src = H1T + (size_t)k * MP + w * HW;
    float s = 0.f;
    #pragma unroll 8
    for (int p = lane; p < HW; p += 32) s += src[p];
    #pragma unroll
    for (int off = 16; off; off >>= 1) s += __shfl_down_sync(0xffffffffu, s, off);
    if (lane == 0) S1T[k * 16 + w] = s;
}

// max over samples
__global__ void max_k(const float* __restrict__ H2T, float* __restrict__ out) {
    int idx = blockIdx.x * 256 + threadIdx.x;
    if (idx >= OUTF * HW) return;
    int o = idx / HW, p = idx - o * HW;
    const float* src = H2T + (size_t)o * MP + p;
    float m = -INFINITY;
    #pragma unroll
    for (int b = 0; b < NB; b++) m = fmaxf(m, src[b * HW]);
    out[idx] = m;
}

// ---------------- fp16 mma.sync GEMM, 64x128 CTA, ldmatrix fragments ---------
// C^T[n][m] = lrelu( sum_k A[m][k]*W[n][k] + bias[n] )
// A packed [m][k2] (K2TOT words per row); W packed [n][k2].
// AGG: A built on the fly from H1T (fp32 [k][MP]) + S1T per-sample sums.
template<int K2TOT, int NTOT, bool AGG>
__global__ __launch_bounds__(256)
void gemm_mma(const uint32_t* __restrict__ AP,
              const float* __restrict__ H1T, const float* __restrict__ S1T,
              const uint32_t* __restrict__ BhP,
              const float* __restrict__ bias, float* __restrict__ CT) {
    extern __shared__ uint32_t smu[];
    constexpr int ROWW  = 20;              // words per row (16 + 4 pad; 80B = 5x16)
    constexpr int ATILE = 64 * ROWW;       // 1280
    constexpr int BTILE = 128 * ROWW;      // 2560
    constexpr int BUFW  = ATILE + BTILE;   // 3840 words
    constexpr int NC    = K2TOT / 16;

    const int tid  = threadIdx.x;
    const int lane = tid & 31;
    const int wid  = tid >> 5;
    const int bm   = blockIdx.y * 64;
    const int bn   = blockIdx.x * 128;
    const int wm   = (wid & 1) * 32;
    const int wn   = (wid >> 1) * 32;
    const int g    = lane >> 2, tg = lane & 3;
    const uint32_t sb = smem_u32(smu);

    // ldmatrix per-lane word offsets
    const int mat = lane >> 3, r8 = lane & 7;
    // A tile [m][k2]: matrices (m0-7,k0-3)(m8-15,k0-3)(m0-7,k4-7)(m8-15,k4-7)
    const int aoff0 = (wm + (mat & 1) * 8 + r8) * ROWW + (mat >> 1) * 4;
    const int aoff1 = aoff0 + 16 * ROWW;
    // B tile [n][k2]: matrices (n0-7,k0-3)(n0-7,k4-7)(n8-15,k0-3)(n8-15,k4-7)
    const int boff0 = ATILE + (wn + (mat >> 1) * 8 + r8) * ROWW + (mat & 1) * 4;
    const int boff1 = boff0 + 16 * ROWW;

    float acc[2][4][4];
    #pragma unroll
    for (int i = 0; i < 2; i++)
        #pragma unroll
        for (int j = 0; j < 4; j++)
            #pragma unroll
            for (int e = 0; e < 4; e++) acc[i][j][e] = 0.f;

    auto load_chunk = [&](int ch) {
        const int st   = ch & 1;
        const int k2_0 = ch * 16;
        const uint32_t bufb = sb + (uint32_t)(st * BUFW) * 4;
        // B tile via cp.async: 128 n-rows x 16 k2 words (4 segs of 16B each)
        #pragma unroll
        for (int i = 0; i < 2; i++) {
            int q   = tid + i * 256;       // 0..511
            int row = q >> 2, seg = q & 3;
            const uint32_t* src = BhP + (size_t)(bn + row) * K2TOT + k2_0 + seg * 4;
            uint32_t dst = bufb + (uint32_t)(ATILE + row * ROWW + seg * 4) * 4;
            CP_ASYNC16(dst, src);
        }
        if (!AGG) {
            // A tile via cp.async: 64 m-rows x 16 k2 words, 1 op/thread
            int row = tid >> 2, seg = tid & 3;
            const uint32_t* src = AP + (size_t)(bm + row) * K2TOT + k2_0 + seg * 4;
            uint32_t dst = bufb + (uint32_t)(row * ROWW + seg * 4) * 4;
            CP_ASYNC16(dst, src);
        } else {
            // A computed: agg(H1) -> fp16x2 words [m][k2]
            uint32_t* bA = smu + st * BUFW;
            const int k0 = ch * 32;
            #pragma unroll
            for (int i = 0; i < 4; i++) {
                int q   = tid + i * 256;   // 0..1023
                int k2l = q >> 6;          // 0..15
                int mi  = q & 63;
                int k   = k0 + 2 * k2l;
                int m   = bm + mi;
                int b = m / HW; if (b > NB - 1) b = NB - 1;
                float db = dinv_of(b);
                float c0 = db * db;
                float cm = (b > 0)      ? db * dinv_of(b - 1) : 0.f;
                float cp = (b < NB - 1) ? db * dinv_of(b + 1) : 0.f;
                const float* h0 = H1T + (size_t)k * MP + m;
                const float* h1 = h0 + MP;
                float v0 = c0 * (__ldg(&S1T[k * 16 + b]) + __ldg(h0));
                float v1 = c0 * (__ldg(&S1T[(k + 1) * 16 + b]) + __ldg(h1));
                if (b > 0) {
                    v0 += cm * __ldg(h0 - HW);
                    v1 += cm * __ldg(h1 - HW);
                }
                if (b < NB - 1) {
                    v0 += cp * __ldg(h0 + HW);
                    v1 += cp * __ldg(h1 + HW);
                }
                bA[mi * ROWW + k2l] = f16x2_pack(v0, v1);
            }
        }
    };

    // prologue
    load_chunk(0);
    CP_COMMIT();

    for (int ch = 0; ch < NC; ch++) {
        if (ch + 1 < NC) load_chunk(ch + 1);
        CP_COMMIT();
        CP_WAIT1();
        __syncthreads();

        const uint32_t stb = sb + (uint32_t)((ch & 1) * BUFW) * 4;

        #pragma unroll
        for (int kk = 0; kk < 2; kk++) {
            const uint32_t kof = (uint32_t)(kk * 8) * 4;
            uint32_t a0[4], a1[4], b0[4], b1[4];
            LDSM_X4(a0[0], a0[1], a0[2], a0[3], stb + (uint32_t)aoff0 * 4 + kof);
            LDSM_X4(a1[0], a1[1], a1[2], a1[3], stb + (uint32_t)aoff1 * 4 + kof);
            LDSM_X4(b0[0], b0[1], b0[2], b0[3], stb + (uint32_t)boff0 * 4 + kof);
            LDSM_X4(b1[0], b1[1], b1[2], b1[3], stb + (uint32_t)boff1 * 4 + kof);
            MMA_F16(acc[0][0], a0[0], a0[1], a0[2], a0[3], b0[0], b0[1]);
            MMA_F16(acc[0][1], a0[0], a0[1], a0[2], a0[3], b0[2], b0[3]);
            MMA_F16(acc[0][2], a0[0], a0[1], a0[2], a0[3], b1[0], b1[1]);
            MMA_F16(acc[0][3], a0[0], a0[1], a0[2], a0[3], b1[2], b1[3]);
            MMA_F16(acc[1][0], a1[0], a1[1], a1[2], a1[3], b0[0], b0[1]);
            MMA_F16(acc[1][1], a1[0], a1[1], a1[2], a1[3], b0[2], b0[3]);
            MMA_F16(acc[1][2], a1[0], a1[1], a1[2], a1[3], b1[0], b1[1]);
            MMA_F16(acc[1][3], a1[0], a1[1], a1[2], a1[3], b1[2], b1[3]);
        }
        __syncthreads();
    }

    // epilogue: bias + leaky relu, store transposed CT[n][m]
    #pragma unroll
    for (int mt = 0; mt < 2; mt++) {
        int m0 = bm + wm + mt * 16 + g;
        bool v0 = m0 < Mrows, v8 = (m0 + 8) < Mrows;
        #pragma unroll
        for (int nt = 0; nt < 4; nt++) {
            int n = bn + wn + nt * 8 + 2 * tg;
            float bb0 = __ldg(&bias[n]), bb1 = __ldg(&bias[n + 1]);
            float c0 = acc[mt][nt][0] + bb0;
            float c1 = acc[mt][nt][1] + bb1;
            float c2 = acc[mt][nt][2] + bb0;
            float c3 = acc[mt][nt][3] + bb1;
            c0 = c0 > 0.f ? c0 : 0.01f * c0;
            c1 = c1 > 0.f ? c1 : 0.01f * c1;
            c2 = c2 > 0.f ? c2 : 0.01f * c2;
            c3 = c3 > 0.f ? c3 : 0.01f * c3;
            if (v0) {
                CT[(size_t)n * MP + m0]       = c0;
                CT[(size_t)(n + 1) * MP + m0] = c1;
            }
            if (v8) {
                CT[(size_t)n * MP + m0 + 8]       = c2;
                CT[(size_t)(n + 1) * MP + m0 + 8] = c3;
            }
        }
    }
}

// ---------------- launcher ----------------------------------------------------
extern "C" void kernel_launch(void* const* d_in, const int* in_sizes, int n_in,
                              void* d_out, int out_size) {
    const float* x  = (const float*)d_in[0];
    const float* W1 = (const float*)d_in[1];
    const float* b1 = (const float*)d_in[2];
    const float* W2 = (const float*)d_in[3];
    const float* b2 = (const float*)d_in[4];
    float* out = (float*)d_out;

    float *S0, *H1T, *S1T, *H2T;
    uint32_t *YP, *W1h, *W2h;
    cudaGetSymbolAddress((void**)&S0,  g_S0);
    cudaGetSymbolAddress((void**)&YP,  g_YP);
    cudaGetSymbolAddress((void**)&W1h, g_W1hP);
    cudaGetSymbolAddress((void**)&W2h, g_W2hP);
    cudaGetSymbolAddress((void**)&H1T, g_H1T);
    cudaGetSymbolAddress((void**)&S1T, g_S1T);
    cudaGetSymbolAddress((void**)&H2T, g_H2T);

    constexpr int SMEM = 2 * 3840 * 4;   // 30720 B
    cudaFuncSetAttribute(gemm_mma<Cc / 2,  HID,  false>,
                         cudaFuncAttributeMaxDynamicSharedMemorySize, SMEM);
    cudaFuncSetAttribute(gemm_mma<HID / 2, OUTF, true>,
                         cudaFuncAttributeMaxDynamicSharedMemorySize, SMEM);

    // 1) per-sample channel sums of x; weights -> packed [n][k2] (linear)
    sum_x_kernel<<<NB * Cc, 256>>>(x, S0);
    wsplit_lin<<<(HID * Cc / 2 + 255) / 256, 256>>>(W1, W1h, HID * Cc / 2);
    wsplit_lin<<<(OUTF * HID / 2 + 255) / 256, 256>>>(W2, W2h, OUTF * HID / 2);

    // 2) aggregation on x -> packed fp16 Y [m][k2]  (grid.y = Cc/8 = 32!)
    agg_x_f16<<<dim3((Mrows + 255) / 256, Cc / 8), 256>>>(x, S0, YP);

    // 3) GEMM1: H1T = lrelu(Y @ W1^T + b1)^T
    gemm_mma<Cc / 2, HID, false><<<dim3(HID / 128, MP / 64), 256, SMEM>>>(
        YP, nullptr, nullptr, W1h, b1, H1T);

    // 4) per-sample sums of H1
    sum_h<<<HID, 256>>>(H1T, S1T);

    // 5) GEMM2 (fused aggregation): H2T = lrelu(agg(H1) @ W2^T + b2)^T
    gemm_mma<HID / 2, OUTF, true><<<dim3(OUTF / 128, MP / 64), 256, SMEM>>>(
        nullptr, H1T, S1T, W2h, b2, H2T);

    // 6) max over samples
    max_k<<<(OUTF * HW + 255) / 256, 256>>>(H2T, out);
}

// round 12
// speedup vs baseline: 1.8137x; 1.4050x over previous
#include <cuda_runtime.h>
#include <cuda_fp16.h>
#include <math.h>
#include <cstdint>

// ---------------- problem constants ----------------------------------------
#define NB    8
#define Cc    256
#define HW    961
#define Mrows 7688
#define MP    7808          // padded M = 61*128
#define HID   512
#define OUTF  256

// ---------------- scratch (device globals; zero-initialized) ----------------
__device__ float    g_S0  [NB * Cc];
__device__ uint32_t g_YP  [MP * (Cc / 2)];     // m-major packed fp16x2 [m][k2]
__device__ uint32_t g_W1hP[HID * (Cc / 2)];    // n-major packed [n][k2]
__device__ uint32_t g_W2hP[OUTF * (HID / 2)];
__device__ uint32_t g_H1P [MP * (HID / 2)];    // H1 packed fp16x2 [m][k2] (pad rows stay 0)
__device__ float    g_P   [NB * 16 * HID];     // partial per-sample sums
__device__ float    g_S1T [HID * 16];

// ---------------- helpers ----------------------------------------------------
__device__ __forceinline__ uint32_t smem_u32(const void* p) {
    uint32_t a;
    asm("{ .reg .u64 t; cvta.to.shared.u64 t, %1; cvt.u32.u64 %0, t; }"
        : "=r"(a) : "l"(p));
    return a;
}

__device__ __forceinline__ float dinv_of(int b) {
    int deg = (b == 0 || b == NB - 1) ? 963 : 964;
    return 1.0f / sqrtf((float)deg);
}

__device__ __forceinline__ uint32_t f16x2_pack(float v0, float v1) {
    __half2 h = __floats2half2_rn(v0, v1);
    return *(uint32_t*)&h;
}

// deterministic float atomic max (sign-split trick; dst must be inited to -inf)
__device__ __forceinline__ void atomicMaxF(float* addr, float v) {
    if (v >= 0.f) atomicMax((int*)addr, __float_as_int(v));
    else          atomicMin((unsigned int*)addr, (unsigned int)__float_as_int(v));
}

#define MMA_F16(d, a0, a1, a2, a3, b0, b1) \
    asm volatile("mma.sync.aligned.m16n8k16.row.col.f32.f16.f16.f32 " \
                 "{%0,%1,%2,%3},{%4,%5,%6,%7},{%8,%9},{%0,%1,%2,%3};" \
                 : "+f"((d)[0]), "+f"((d)[1]), "+f"((d)[2]), "+f"((d)[3]) \
                 : "r"(a0), "r"(a1), "r"(a2), "r"(a3), "r"(b0), "r"(b1))

#define LDSM_X4(r0, r1, r2, r3, addr) \
    asm volatile("ldmatrix.sync.aligned.m8n8.x4.shared.b16 {%0,%1,%2,%3}, [%4];" \
                 : "=r"(r0), "=r"(r1), "=r"(r2), "=r"(r3) : "r"(addr))

#define CP_ASYNC16(dst32, src) \
    asm volatile("cp.async.cg.shared.global [%0], [%1], 16;" :: "r"(dst32), "l"(src))
#define CP_COMMIT()  asm volatile("cp.async.commit_group;" ::: "memory")
#define CP_WAIT1()   asm volatile("cp.async.wait_group 1;" ::: "memory")

// ---------------- small kernels ----------------------------------------------
__global__ void sum_x_kernel(const float* __restrict__ x, float* __restrict__ S0) {
    int bc = blockIdx.x;
    const float* src = x + (size_t)bc * HW;
    float s = 0.f;
    for (int p = threadIdx.x; p < HW; p += 256) s += src[p];
    __shared__ float red[8];
    #pragma unroll
    for (int off = 16; off; off >>= 1) s += __shfl_down_sync(0xffffffffu, s, off);
    if ((threadIdx.x & 31) == 0) red[threadIdx.x >> 5] = s;
    __syncthreads();
    if (threadIdx.x < 8) {
        s = red[threadIdx.x];
        #pragma unroll
        for (int off = 4; off; off >>= 1) s += __shfl_down_sync(0xffu, s, off);
        if (threadIdx.x == 0) S0[bc] = s;
    }
}

// W[Nr][Kc] row-major fp32 -> packed fp16x2 [n][k2] (pure linear pack)
__global__ void wsplit_lin(const float* __restrict__ W, uint32_t* __restrict__ WhP,
                           int total2) {
    int i = blockIdx.x * 256 + threadIdx.x;
    if (i < total2) {
        float2 v = ((const float2*)W)[i];
        WhP[i] = f16x2_pack(v.x, v.y);
    }
}

// init output to -inf
__global__ void init_out(float* __restrict__ out) {
    int i = blockIdx.x * 256 + threadIdx.x;
    if (i < OUTF * HW) out[i] = __int_as_float(0xFF800000);
}

// aggregation on x -> m-major packed fp16x2 [m][Cc/2]; 8 channels per thread
__global__ void agg_x_f16(const float* __restrict__ x, const float* __restrict__ S0,
                          uint32_t* __restrict__ YP) {
    int m  = blockIdx.x * 256 + threadIdx.x;
    if (m >= Mrows) return;
    int cq = blockIdx.y;                      // 0..31
    int b = m / HW, p = m - b * HW;
    float db = dinv_of(b);
    float c0 = db * db;
    float cm = (b > 0)      ? db * dinv_of(b - 1) : 0.f;
    float cp = (b < NB - 1) ? db * dinv_of(b + 1) : 0.f;
    uint32_t w[4];
    #pragma unroll
    for (int j = 0; j < 4; j++) {
        float v2[2];
        #pragma unroll
        for (int e = 0; e < 2; e++) {
            int c = cq * 8 + j * 2 + e;
            size_t xi = (size_t)(b * Cc + c) * HW + p;
            float vv = c0 * (__ldg(&S0[b * Cc + c]) + __ldg(&x[xi]));
            if (b > 0)      vv += cm * __ldg(&x[xi - (size_t)Cc * HW]);
            if (b < NB - 1) vv += cp * __ldg(&x[xi + (size_t)Cc * HW]);
            v2[e] = vv;
        }
        w[j] = f16x2_pack(v2[0], v2[1]);
    }
    *(uint4*)(YP + (size_t)m * (Cc / 2) + cq * 4) = make_uint4(w[0], w[1], w[2], w[3]);
}

// per-sample column sums of H1P (fp16 packed [m][256]) -> partial P
__global__ void sum_h_part(const uint32_t* __restrict__ H1P, float* __restrict__ P) {
    int b = blockIdx.x, chunk = blockIdx.y;   // 8 x 16
    int t = threadIdx.x;                      // k2 word 0..255
    int p0 = chunk * 61;
    int p1 = p0 + 61; if (p1 > HW) p1 = HW;
    float s0 = 0.f, s1 = 0.f;
    for (int p = p0; p < p1; p++) {
        uint32_t w = __ldg(&H1P[(size_t)(b * HW + p) * (HID / 2) + t]);
        __half2 h = *(__half2*)&w;
        float2 f = __half22float2(h);
        s0 += f.x; s1 += f.y;
    }
    P[((size_t)(b * 16 + chunk)) * HID + 2 * t]     = s0;
    P[((size_t)(b * 16 + chunk)) * HID + 2 * t + 1] = s1;
}

__global__ void sum_h_red(const float* __restrict__ P, float* __restrict__ S1T) {
    int idx = blockIdx.x * 256 + threadIdx.x;     // 0..4095
    if (idx >= HID * NB) return;
    int k = idx >> 3, b = idx & 7;
    float s = 0.f;
    #pragma unroll
    for (int c = 0; c < 16; c++) s += P[((size_t)(b * 16 + c)) * HID + k];
    S1T[k * 16 + b] = s;
}

// ---------------- fp16 mma.sync GEMM, 64x128 CTA, ldmatrix fragments ---------
// MODE 0: A from AP (cp.async); epilogue -> packed fp16x2 H1P [m][NTOT/2]
// MODE 1: A computed from H1P (fp16 [m][k2]) + S1T; epilogue -> atomicMax out
template<int K2TOT, int NTOT, int MODE>
__global__ __launch_bounds__(256)
void gemm_mma(const uint32_t* __restrict__ AP,
              const uint32_t* __restrict__ H1P, const float* __restrict__ S1T,
              const uint32_t* __restrict__ BhP,
              const float* __restrict__ bias, void* __restrict__ OUTP) {
    extern __shared__ uint32_t smu[];
    constexpr int ROWW  = 20;              // words per row (16 + 4 pad; 80B = 5x16)
    constexpr int ATILE = 64 * ROWW;
    constexpr int BTILE = 128 * ROWW;
    constexpr int BUFW  = ATILE + BTILE;   // 3840 words
    constexpr int NC    = K2TOT / 16;

    const int tid  = threadIdx.x;
    const int lane = tid & 31;
    const int wid  = tid >> 5;
    const int bm   = blockIdx.y * 64;
    const int bn   = blockIdx.x * 128;
    const int wm   = (wid & 1) * 32;
    const int wn   = (wid >> 1) * 32;
    const int g    = lane >> 2, tg = lane & 3;
    const uint32_t sb = smem_u32(smu);

    const int mat = lane >> 3, r8 = lane & 7;
    const int aoff0 = (wm + (mat & 1) * 8 + r8) * ROWW + (mat >> 1) * 4;
    const int aoff1 = aoff0 + 16 * ROWW;
    const int boff0 = ATILE + (wn + (mat >> 1) * 8 + r8) * ROWW + (mat & 1) * 4;
    const int boff1 = boff0 + 16 * ROWW;

    float acc[2][4][4];
    #pragma unroll
    for (int i = 0; i < 2; i++)
        #pragma unroll
        for (int j = 0; j < 4; j++)
            #pragma unroll
            for (int e = 0; e < 4; e++) acc[i][j][e] = 0.f;

    auto load_chunk = [&](int ch) {
        const int st   = ch & 1;
        const int k2_0 = ch * 16;
        const uint32_t bufb = sb + (uint32_t)(st * BUFW) * 4;
        // B tile via cp.async: 128 n-rows x 16 k2 words
        #pragma unroll
        for (int i = 0; i < 2; i++) {
            int q   = tid + i * 256;
            int row = q >> 2, seg = q & 3;
            const uint32_t* src = BhP + (size_t)(bn + row) * K2TOT + k2_0 + seg * 4;
            uint32_t dst = bufb + (uint32_t)(ATILE + row * ROWW + seg * 4) * 4;
            CP_ASYNC16(dst, src);
        }
        if (MODE == 0) {
            int row = tid >> 2, seg = tid & 3;
            const uint32_t* src = AP + (size_t)(bm + row) * K2TOT + k2_0 + seg * 4;
            uint32_t dst = bufb + (uint32_t)(row * ROWW + seg * 4) * 4;
            CP_ASYNC16(dst, src);
        } else {
            // A computed: agg of fp16 H1P -> fp16x2 words [m][k2]
            uint32_t* bA = smu + st * BUFW;
            int mi = tid >> 2, seg = tid & 3;
            int m = bm + mi;
            int b = m / HW; if (b > NB - 1) b = NB - 1;
            float db = dinv_of(b);
            float c0 = db * db;
            bool hasm = (b > 0), hasp = (b < NB - 1);
            float cm = hasm ? db * dinv_of(b - 1) : 0.f;
            float cp = hasp ? db * dinv_of(b + 1) : 0.f;
            const uint32_t* hr = H1P + (size_t)m * K2TOT + k2_0 + seg * 4;
            uint4 h  = *(const uint4*)hr;
            uint4 hm = hasm ? *(const uint4*)(hr - (size_t)HW * K2TOT)
                            : make_uint4(0, 0, 0, 0);
            uint4 hp = hasp ? *(const uint4*)(hr + (size_t)HW * K2TOT)
                            : make_uint4(0, 0, 0, 0);
            const uint32_t* hw  = (const uint32_t*)&h;
            const uint32_t* hmw = (const uint32_t*)&hm;
            const uint32_t* hpw = (const uint32_t*)&hp;
            #pragma unroll
            for (int j = 0; j < 4; j++) {
                int k2 = k2_0 + seg * 4 + j;
                int k  = 2 * k2;
                float2 f  = __half22float2(*(__half2*)&hw[j]);
                float2 fm = __half22float2(*(__half2*)&hmw[j]);
                float2 fp = __half22float2(*(__half2*)&hpw[j]);
                float v0 = c0 * (__ldg(&S1T[k * 16 + b]) + f.x) + cm * fm.x + cp * fp.x;
                float v1 = c0 * (__ldg(&S1T[(k + 1) * 16 + b]) + f.y) + cm * fm.y + cp * fp.y;
                bA[mi * ROWW + seg * 4 + j] = f16x2_pack(v0, v1);
            }
        }
    };

    // prologue
    load_chunk(0);
    CP_COMMIT();

    for (int ch = 0; ch < NC; ch++) {
        if (ch + 1 < NC) load_chunk(ch + 1);
        CP_COMMIT();
        CP_WAIT1();
        __syncthreads();

        const uint32_t stb = sb + (uint32_t)((ch & 1) * BUFW) * 4;

        #pragma unroll
        for (int kk = 0; kk < 2; kk++) {
            const uint32_t kof = (uint32_t)(kk * 8) * 4;
            uint32_t a0[4], a1[4], b0[4], b1[4];
            LDSM_X4(a0[0], a0[1], a0[2], a0[3], stb + (uint32_t)aoff0 * 4 + kof);
            LDSM_X4(a1[0], a1[1], a1[2], a1[3], stb + (uint32_t)aoff1 * 4 + kof);
            LDSM_X4(b0[0], b0[1], b0[2], b0[3], stb + (uint32_t)boff0 * 4 + kof);
            LDSM_X4(b1[0], b1[1], b1[2], b1[3], stb + (uint32_t)boff1 * 4 + kof);
            MMA_F16(acc[0][0], a0[0], a0[1], a0[2], a0[3], b0[0], b0[1]);
            MMA_F16(acc[0][1], a0[0], a0[1], a0[2], a0[3], b0[2], b0[3]);
            MMA_F16(acc[0][2], a0[0], a0[1], a0[2], a0[3], b1[0], b1[1]);
            MMA_F16(acc[0][3], a0[0], a0[1], a0[2], a0[3], b1[2], b1[3]);
            MMA_F16(acc[1][0], a1[0], a1[1], a1[2], a1[3], b0[0], b0[1]);
            MMA_F16(acc[1][1], a1[0], a1[1], a1[2], a1[3], b0[2], b0[3]);
            MMA_F16(acc[1][2], a1[0], a1[1], a1[2], a1[3], b1[0], b1[1]);
            MMA_F16(acc[1][3], a1[0], a1[1], a1[2], a1[3], b1[2], b1[3]);
        }
        __syncthreads();
    }

    // epilogue
    #pragma unroll
    for (int mt = 0; mt < 2; mt++) {
        int m0 = bm + wm + mt * 16 + g;
        bool v0 = m0 < Mrows, v8 = (m0 + 8) < Mrows;
        #pragma unroll
        for (int nt = 0; nt < 4; nt++) {
            int n = bn + wn + nt * 8 + 2 * tg;
            float bb0 = __ldg(&bias[n]), bb1 = __ldg(&bias[n + 1]);
            float c0 = acc[mt][nt][0] + bb0;
            float c1 = acc[mt][nt][1] + bb1;
            float c2 = acc[mt][nt][2] + bb0;
            float c3 = acc[mt][nt][3] + bb1;
            c0 = c0 > 0.f ? c0 : 0.01f * c0;
            c1 = c1 > 0.f ? c1 : 0.01f * c1;
            c2 = c2 > 0.f ? c2 : 0.01f * c2;
            c3 = c3 > 0.f ? c3 : 0.01f * c3;
            if (MODE == 0) {
                uint32_t* H = (uint32_t*)OUTP;
                int n2 = n >> 1;
                if (v0) H[(size_t)m0 * (NTOT / 2) + n2]       = f16x2_pack(c0, c1);
                if (v8) H[(size_t)(m0 + 8) * (NTOT / 2) + n2] = f16x2_pack(c2, c3);
            } else {
                float* out = (float*)OUTP;
                if (v0) {
                    int b = m0 / HW, p = m0 - b * HW;
                    atomicMaxF(out + (size_t)n * HW + p, c0);
                    atomicMaxF(out + (size_t)(n + 1) * HW + p, c1);
                }
                if (v8) {
                    int m8 = m0 + 8;
                    int b = m8 / HW, p = m8 - b * HW;
                    atomicMaxF(out + (size_t)n * HW + p, c2);
                    atomicMaxF(out + (size_t)(n + 1) * HW + p, c3);
                }
            }
        }
    }
}

// ---------------- launcher ----------------------------------------------------
extern "C" void kernel_launch(void* const* d_in, const int* in_sizes, int n_in,
                              void* d_out, int out_size) {
    const float* x  = (const float*)d_in[0];
    const float* W1 = (const float*)d_in[1];
    const float* b1 = (const float*)d_in[2];
    const float* W2 = (const float*)d_in[3];
    const float* b2 = (const float*)d_in[4];
    float* out = (float*)d_out;

    float *S0, *P, *S1T;
    uint32_t *YP, *W1h, *W2h, *H1P;
    cudaGetSymbolAddress((void**)&S0,  g_S0);
    cudaGetSymbolAddress((void**)&YP,  g_YP);
    cudaGetSymbolAddress((void**)&W1h, g_W1hP);
    cudaGetSymbolAddress((void**)&W2h, g_W2hP);
    cudaGetSymbolAddress((void**)&H1P, g_H1P);
    cudaGetSymbolAddress((void**)&P,   g_P);
    cudaGetSymbolAddress((void**)&S1T, g_S1T);

    constexpr int SMEM = 2 * 3840 * 4;   // 30720 B
    cudaFuncSetAttribute(gemm_mma<Cc / 2,  HID,  0>,
                         cudaFuncAttributeMaxDynamicSharedMemorySize, SMEM);
    cudaFuncSetAttribute(gemm_mma<HID / 2, OUTF, 1>,
                         cudaFuncAttributeMaxDynamicSharedMemorySize, SMEM);

    // 1) sums of x; weights -> packed [n][k2]; out -> -inf
    sum_x_kernel<<<NB * Cc, 256>>>(x, S0);
    wsplit_lin<<<(HID * Cc / 2 + 255) / 256, 256>>>(W1, W1h, HID * Cc / 2);
    wsplit_lin<<<(OUTF * HID / 2 + 255) / 256, 256>>>(W2, W2h, OUTF * HID / 2);
    init_out<<<(OUTF * HW + 255) / 256, 256>>>(out);

    // 2) aggregation on x -> packed fp16 Y [m][k2]
    agg_x_f16<<<dim3((Mrows + 255) / 256, Cc / 8), 256>>>(x, S0, YP);

    // 3) GEMM1: H1P = pack(lrelu(Y @ W1^T + b1))  [m][k2]
    gemm_mma<Cc / 2, HID, 0><<<dim3(HID / 128, MP / 64), 256, SMEM>>>(
        YP, nullptr, nullptr, W1h, b1, H1P);

    // 4) per-sample sums of H1 (2-stage, deterministic)
    sum_h_part<<<dim3(NB, 16), 256>>>(H1P, P);
    sum_h_red<<<(HID * NB + 255) / 256, 256>>>(P, S1T);

    // 5) GEMM2 (fused agg + fused max): out = max_b lrelu(agg(H1) @ W2^T + b2)
    gemm_mma<HID / 2, OUTF, 1><<<dim3(OUTF / 128, MP / 64), 256, SMEM>>>(
        nullptr, H1P, S1T, W2h, b2, out);
}